// round 17
// baseline (speedup 1.0000x reference)
#include <cuda_runtime.h>
#include <cuda.h>
#include <math.h>

// Top2Router: x[16384,2048] fp32, W[8,2048], b[8]
// out (fp32 concat): top2_val[N*2] | top2_idx[N*2] | gate[N*8]
//
// DUAL-ENGINE kernel: warps 0-7 consume k<1024 via TMA ring (R14-proven:
// 16 chunks, 5 stages, distance-4, named barrier bar.sync 1,256);
// warps 8-15 stream k>=1024 directly via LDG (R6-proven: 4-token groups,
// lane=k-pair, planar W, butterfly reduce, barrier-free). Halves meet at
// one final __syncthreads; combine + softmax + top2.

#define D_MODEL  2048
#define NEXP     8
#define KHALF    1024
#define KCHUNK   64
#define NCHUNK   (KHALF / KCHUNK)     // 16
#define NSTAGE   5
#define THREADS  512
#define HIPAD    112
#define TILE_F   (32 * HIPAD)          // 3584
#define STAGE_F  (2 * TILE_F)          // 7168

// smem float offsets
#define OFF_RING 0
#define OFF_WT   (NSTAGE * STAGE_F)            // 35840 (8192 floats)
#define OFF_WZ   (OFF_WT + 8192)               // 44032 (8192 floats = 4096 u64)
#define OFF_LGS2 (OFF_WZ + 8192)               // 52224 (896 floats)
#define OFF_LGS  (OFF_LGS2 + 896)              // 53120 (896 floats)
#define OFF_END  (OFF_LGS + 896)               // 54016

typedef unsigned long long u64;

__device__ __forceinline__ void mbar_init(unsigned mb, unsigned count) {
    asm volatile("mbarrier.init.shared.b64 [%0], %1;" :: "r"(mb), "r"(count) : "memory");
}
__device__ __forceinline__ void mbar_expect_tx(unsigned mb, unsigned bytes) {
    asm volatile("mbarrier.arrive.expect_tx.shared.b64 _, [%0], %1;"
                 :: "r"(mb), "r"(bytes) : "memory");
}
__device__ __forceinline__ void mbar_wait(unsigned mb, unsigned parity) {
    asm volatile(
        "{\n\t.reg .pred P;\n"
        "W_%=:\n\t"
        "mbarrier.try_wait.parity.acquire.cta.shared::cta.b64 P, [%0], %1, 0x989680;\n\t"
        "@P bra D_%=;\n\t"
        "bra W_%=;\n"
        "D_%=:\n\t}"
        :: "r"(mb), "r"(parity) : "memory");
}
__device__ __forceinline__ void tma2d(unsigned dst, const CUtensorMap* map,
                                      int c0, int c1, unsigned mb) {
    asm volatile(
        "cp.async.bulk.tensor.2d.shared::cta.global.tile.mbarrier::complete_tx::bytes "
        "[%0], [%1, {%2, %3}], [%4];"
        :: "r"(dst), "l"(map), "r"(c0), "r"(c1), "r"(mb) : "memory");
}
__device__ __forceinline__ u64 splat2(float v) {
    u64 r; asm("mov.b64 %0, {%1, %1};" : "=l"(r) : "f"(v)); return r;
}
__device__ __forceinline__ void ffma2(u64& a, u64 x, u64 w) {
    asm("fma.rn.f32x2 %0, %1, %2, %0;" : "+l"(a) : "l"(x), "l"(w));
}
__device__ __forceinline__ void add2(u64& a, u64 o) {
    asm("add.rn.f32x2 %0, %0, %1;" : "+l"(a) : "l"(o));
}

__global__ __launch_bounds__(THREADS, 1)
void top2_router_kernel(const __grid_constant__ CUtensorMap mapHi,
                        const __grid_constant__ CUtensorMap mapLo,
                        const float* __restrict__ x,
                        const float* __restrict__ W,
                        const float* __restrict__ b,
                        float* __restrict__ out,
                        int n_tok, int hi)
{
    extern __shared__ float smem[];
    float* ring = smem + OFF_RING;
    float* wt   = smem + OFF_WT;                 // wt[k*8+e], k<1024 (broadcast)
    u64*   wz   = reinterpret_cast<u64*>(smem + OFF_WZ);  // planar, k>=1024
    float2* lgs2 = reinterpret_cast<float2*>(smem + OFF_LGS2);
    float* lgs  = smem + OFF_LGS;

    const unsigned smem_u32 = (unsigned)__cvta_generic_to_shared(smem);
    const unsigned ring_u32 = smem_u32;
    const unsigned mbar0    = smem_u32 + OFF_END * 4u;
    const unsigned stageBytes = (unsigned)STAGE_F * 4u;
    const unsigned tileBytes  = (unsigned)TILE_F * 4u;

    const int tid  = threadIdx.x;
    const int w    = tid >> 5;
    const int lane = tid & 31;

    // unit-1 balanced token range
    const int G     = gridDim.x;
    const int tokenBase = (int)(((long long)blockIdx.x       * n_tok) / G);
    const int tokenEnd  = (int)(((long long)(blockIdx.x + 1) * n_tok) / G);
    const int ntok_b    = tokenEnd - tokenBase;  // hi or hi-1

    const CUtensorMap* mp = (ntok_b == hi) ? &mapHi : &mapLo;
    const unsigned chunkBytes = (unsigned)ntok_b * 256u;

    // ---- kick off TMA first (DRAM busy during W staging)
    if (tid == 0) {
        #pragma unroll
        for (int s = 0; s < NSTAGE; ++s) mbar_init(mbar0 + s * 8, 1);
        asm volatile("fence.proxy.async.shared::cta;" ::: "memory");
        #pragma unroll
        for (int c = 0; c < 3; ++c) {
            unsigned mb  = mbar0 + (c % NSTAGE) * 8;
            unsigned dst = ring_u32 + (unsigned)(c % NSTAGE) * stageBytes;
            mbar_expect_tx(mb, chunkBytes);
            tma2d(dst,             mp, c * KCHUNK,      tokenBase, mb);
            tma2d(dst + tileBytes, mp, c * KCHUNK + 32, tokenBase, mb);
        }
    }

    // ---- stage W (both layouts)
    #pragma unroll
    for (int i = 0; i < 16; ++i) {               // 8192 floats, k<1024
        int idx = tid + i * THREADS;
        int e = idx >> 10;
        int k = idx & 1023;
        wt[k * NEXP + e] = W[e * D_MODEL + k];
    }
    #pragma unroll
    for (int i = 0; i < 8; ++i) {                // 4096 u64, k>=1024
        int q     = tid + i * THREADS;
        int plane = q >> 9;                      // 0..7
        int kkl   = q & 511;
        int j     = plane >> 2;
        int p     = plane & 3;
        int k     = KHALF + 2 * kkl + j;
        float lo  = W[(2 * p) * D_MODEL + k];
        float hv  = W[(2 * p + 1) * D_MODEL + k];
        u64 v; asm("mov.b64 %0, {%1, %2};" : "=l"(v) : "f"(lo), "f"(hv));
        wz[q] = v;
    }
    __syncthreads();

    if (tid == 0) {      // complete 4-deep prologue
        unsigned mb  = mbar0 + 3 * 8;
        unsigned dst = ring_u32 + 3u * stageBytes;
        mbar_expect_tx(mb, chunkBytes);
        tma2d(dst,             mp, 3 * KCHUNK,      tokenBase, mb);
        tma2d(dst + tileBytes, mp, 3 * KCHUNK + 32, tokenBase, mb);
    }

    const int tokLim = ntok_b - 1;

    if (w < 8) {
        // ================= TMA half: k < 1024 =================
        const u64* wt64 = reinterpret_cast<const u64*>(wt);
        const int tsel = w >> 2;                 // tile 0/1
        const int ws   = w & 3;                  // slot base (slots ws, ws+4)

        u64 acc[4][4];
        #pragma unroll
        for (int t = 0; t < 4; ++t)
            #pragma unroll
            for (int p = 0; p < 4; ++p) acc[t][p] = 0ull;

        for (int c = 0; c < NCHUNK; ++c) {
            mbar_wait(mbar0 + (c % NSTAGE) * 8, (unsigned)((c / NSTAGE) & 1));
            asm volatile("bar.sync 1, 256;" ::: "memory");

            if (tid == 0 && c + 4 < NCHUNK) {
                int cc = c + 4;
                unsigned mb  = mbar0 + (cc % NSTAGE) * 8;
                unsigned dst = ring_u32 + (unsigned)(cc % NSTAGE) * stageBytes;
                mbar_expect_tx(mb, chunkBytes);
                tma2d(dst,             mp, cc * KCHUNK,      tokenBase, mb);
                tma2d(dst + tileBytes, mp, cc * KCHUNK + 32, tokenBase, mb);
            }

            const float* tile = ring + (c % NSTAGE) * STAGE_F + tsel * TILE_F;

            float4 xv[4][2];
            #pragma unroll
            for (int t = 0; t < 4; ++t) {
                int tok = lane + t * 32;
                int tokc = tok > tokLim ? tokLim : tok;
                const float4* rowp = reinterpret_cast<const float4*>(tile + tokc * 32);
                xv[t][0] = rowp[ws       ^ (tokc & 7)];
                xv[t][1] = rowp[(ws + 4) ^ (tokc & 7)];
            }

            #pragma unroll
            for (int s2 = 0; s2 < 2; ++s2) {
                #pragma unroll
                for (int j = 0; j < 4; ++j) {
                    int kg = c * KCHUNK + tsel * 32 + (ws + s2 * 4) * 4 + j;
                    u64 wp0 = wt64[kg * 4 + 0];
                    u64 wp1 = wt64[kg * 4 + 1];
                    u64 wp2 = wt64[kg * 4 + 2];
                    u64 wp3 = wt64[kg * 4 + 3];
                    #pragma unroll
                    for (int t = 0; t < 4; ++t) {
                        const float4& v = xv[t][s2];
                        float xk = (j == 0) ? v.x : (j == 1) ? v.y
                                 : (j == 2) ? v.z : v.w;
                        u64 xx = splat2(xk);
                        ffma2(acc[t][0], xx, wp0);
                        ffma2(acc[t][1], xx, wp1);
                        ffma2(acc[t][2], xx, wp2);
                        ffma2(acc[t][3], xx, wp3);
                    }
                }
            }
        }
        asm volatile("bar.sync 1, 256;" ::: "memory");  // ring now free

        // dump partials into ring region: red[(w*HIPAD + tok)*4 + p]
        float2* red = reinterpret_cast<float2*>(ring);
        #pragma unroll
        for (int t = 0; t < 4; ++t) {
            int tok = lane + t * 32;
            if (tok < HIPAD) {
                #pragma unroll
                for (int p = 0; p < 4; ++p) {
                    float lo, hv;
                    asm("mov.b64 {%0, %1}, %2;" : "=f"(lo), "=f"(hv) : "l"(acc[t][p]));
                    red[(w * HIPAD + tok) * 4 + p] = make_float2(lo, hv);
                }
            }
        }
    } else {
        // ================= LDG half: k >= 1024 =================
        const int u  = w - 8;
        const int su = (u * ntok_b) >> 3;
        const int eu = ((u + 1) * ntok_b) >> 3;

        for (int g0 = su; g0 < eu; g0 += 4) {
            int tk[4];
            #pragma unroll
            for (int i = 0; i < 4; ++i) {
                int t = g0 + i;
                tk[i] = t > eu - 1 ? eu - 1 : t;
            }
            const float* rp[4];
            #pragma unroll
            for (int i = 0; i < 4; ++i)
                rp[i] = x + (size_t)(tokenBase + tk[i]) * D_MODEL + KHALF + 2 * lane;

            u64 acc[4][4];
            #pragma unroll
            for (int i = 0; i < 4; ++i)
                #pragma unroll
                for (int p = 0; p < 4; ++p) acc[i][p] = 0ull;

            float2 xc[4];
            #pragma unroll
            for (int i = 0; i < 4; ++i)
                xc[i] = *reinterpret_cast<const float2*>(rp[i]);

            #pragma unroll 1
            for (int s = 0; s < 16; ++s) {
                float2 xn[4];
                if (s + 1 < 16) {
                    #pragma unroll
                    for (int i = 0; i < 4; ++i)
                        xn[i] = *reinterpret_cast<const float2*>(rp[i] + (s + 1) * 64);
                }
                const int kkl = s * 32 + lane;
                u64 wa0 = wz[(0 * 4 + 0) * 512 + kkl];
                u64 wa1 = wz[(0 * 4 + 1) * 512 + kkl];
                u64 wa2 = wz[(0 * 4 + 2) * 512 + kkl];
                u64 wa3 = wz[(0 * 4 + 3) * 512 + kkl];
                u64 wb0 = wz[(1 * 4 + 0) * 512 + kkl];
                u64 wb1 = wz[(1 * 4 + 1) * 512 + kkl];
                u64 wb2 = wz[(1 * 4 + 2) * 512 + kkl];
                u64 wb3 = wz[(1 * 4 + 3) * 512 + kkl];
                #pragma unroll
                for (int i = 0; i < 4; ++i) {
                    u64 xa = splat2(xc[i].x);
                    u64 xb = splat2(xc[i].y);
                    ffma2(acc[i][0], xa, wa0);
                    ffma2(acc[i][1], xa, wa1);
                    ffma2(acc[i][2], xa, wa2);
                    ffma2(acc[i][3], xa, wa3);
                    ffma2(acc[i][0], xb, wb0);
                    ffma2(acc[i][1], xb, wb1);
                    ffma2(acc[i][2], xb, wb2);
                    ffma2(acc[i][3], xb, wb3);
                }
                if (s + 1 < 16) {
                    #pragma unroll
                    for (int i = 0; i < 4; ++i) xc[i] = xn[i];
                }
            }

            // butterfly reduce across lanes
            #pragma unroll
            for (int off = 16; off > 0; off >>= 1) {
                #pragma unroll
                for (int i = 0; i < 4; ++i)
                    #pragma unroll
                    for (int p = 0; p < 4; ++p) {
                        u64 o = __shfl_xor_sync(0xffffffffu, acc[i][p], off);
                        add2(acc[i][p], o);
                    }
            }
            if (lane < 4) {
                #pragma unroll
                for (int p = 0; p < 4; ++p) {
                    float lo, hv;
                    asm("mov.b64 {%0, %1}, %2;" : "=f"(lo), "=f"(hv) : "l"(acc[lane][p]));
                    lgs2[tk[lane] * 4 + p] = make_float2(lo, hv);
                }
            }
        }
    }
    __syncthreads();

    // ---- combine halves: logits = sum(8 TMA partials) + LDG partial + bias
    {
        float2* red = reinterpret_cast<float2*>(ring);
        if (tid < ntok_b * 4) {
            int tok = tid >> 2;
            int p   = tid & 3;
            float2 s = lgs2[tok * 4 + p];
            #pragma unroll
            for (int ww = 0; ww < 8; ++ww) {
                float2 v = red[(ww * HIPAD + tok) * 4 + p];
                s.x += v.x; s.y += v.y;
            }
            s.x += b[2 * p];
            s.y += b[2 * p + 1];
            reinterpret_cast<float2*>(lgs)[tok * 4 + p] = s;
        }
    }
    __syncthreads();

    // ---- per-token softmax + stable top2
    if (tid < ntok_b) {
        const int g = tokenBase + tid;
        float gv[NEXP];
        float mx = -INFINITY;
        #pragma unroll
        for (int e = 0; e < NEXP; ++e) {
            gv[e] = lgs[tid * NEXP + e];
            mx = fmaxf(mx, gv[e]);
        }
        float ssum = 0.f;
        #pragma unroll
        for (int e = 0; e < NEXP; ++e) {
            gv[e] = __expf(gv[e] - mx);
            ssum += gv[e];
        }
        float inv = 1.f / ssum;
        #pragma unroll
        for (int e = 0; e < NEXP; ++e) gv[e] *= inv;

        float* gate_out = out + (size_t)n_tok * 4;
        float4 g0 = make_float4(gv[0], gv[1], gv[2], gv[3]);
        float4 g1 = make_float4(gv[4], gv[5], gv[6], gv[7]);
        *reinterpret_cast<float4*>(gate_out + (size_t)g * NEXP)     = g0;
        *reinterpret_cast<float4*>(gate_out + (size_t)g * NEXP + 4) = g1;

        int i1 = 0; float v1 = gv[0];
        #pragma unroll
        for (int e = 1; e < NEXP; ++e)
            if (gv[e] > v1) { v1 = gv[e]; i1 = e; }
        int i2 = -1; float v2 = -INFINITY;
        #pragma unroll
        for (int e = 0; e < NEXP; ++e)
            if (e != i1 && gv[e] > v2) { v2 = gv[e]; i2 = e; }

        *reinterpret_cast<float2*>(out + (size_t)g * 2) = make_float2(v1, v2);
        float* idx_out = out + (size_t)n_tok * 2;
        *reinterpret_cast<float2*>(idx_out + (size_t)g * 2) =
            make_float2((float)i1, (float)i2);
    }
}

// ---------------------------------------------------------------------------

typedef CUresult (*EncodeTiledFn)(
    CUtensorMap*, CUtensorMapDataType, cuuint32_t, void*,
    const cuuint64_t*, const cuuint64_t*, const cuuint32_t*, const cuuint32_t*,
    CUtensorMapInterleave, CUtensorMapSwizzle, CUtensorMapL2promotion,
    CUtensorMapFloatOOBfill);

static CUtensorMap g_mapHi, g_mapLo;
static const void* g_last_x = nullptr;
static int g_nsm = 0, g_hi = 0, g_smem = 0;

static void build_maps(const float* x, int n_tok, int hi, int lo)
{
    EncodeTiledFn enc = nullptr;
    cudaDriverEntryPointQueryResult qr;
    cudaGetDriverEntryPoint("cuTensorMapEncodeTiled", (void**)&enc,
                            cudaEnableDefault, &qr);
    cuuint64_t dims[2]    = {(cuuint64_t)D_MODEL, (cuuint64_t)n_tok};
    cuuint64_t strides[1] = {(cuuint64_t)D_MODEL * 4};
    cuuint32_t elem[2]    = {1, 1};
    cuuint32_t boxH[2]    = {32, (cuuint32_t)hi};
    cuuint32_t boxL[2]    = {32, (cuuint32_t)lo};
    enc(&g_mapHi, CU_TENSOR_MAP_DATA_TYPE_FLOAT32, 2, (void*)x,
        dims, strides, boxH, elem,
        CU_TENSOR_MAP_INTERLEAVE_NONE, CU_TENSOR_MAP_SWIZZLE_128B,
        CU_TENSOR_MAP_L2_PROMOTION_L2_128B, CU_TENSOR_MAP_FLOAT_OOB_FILL_NONE);
    enc(&g_mapLo, CU_TENSOR_MAP_DATA_TYPE_FLOAT32, 2, (void*)x,
        dims, strides, boxL, elem,
        CU_TENSOR_MAP_INTERLEAVE_NONE, CU_TENSOR_MAP_SWIZZLE_128B,
        CU_TENSOR_MAP_L2_PROMOTION_L2_128B, CU_TENSOR_MAP_FLOAT_OOB_FILL_NONE);
}

extern "C" void kernel_launch(void* const* d_in, const int* in_sizes, int n_in,
                              void* d_out, int out_size)
{
    const float* x = (const float*)d_in[0];
    const float* W = (const float*)d_in[1];
    const float* b = (const float*)d_in[2];
    float* out = (float*)d_out;

    const int n_tok = in_sizes[0] / D_MODEL;     // 16384

    if (g_nsm == 0) {
        cudaDeviceProp prop;
        cudaGetDeviceProperties(&prop, 0);
        g_nsm = prop.multiProcessorCount;        // 152 on GB300
        g_hi = (n_tok + g_nsm - 1) / g_nsm;      // 108
        g_smem = OFF_END * 4 + 64;               // ~216.1 KB
        cudaFuncSetAttribute(top2_router_kernel,
                             cudaFuncAttributeMaxDynamicSharedMemorySize, g_smem);
        build_maps(x, n_tok, g_hi, g_hi - 1);
        g_last_x = x;
    } else if (g_last_x != x) {
        build_maps(x, n_tok, g_hi, g_hi - 1);
        g_last_x = x;
    }

    top2_router_kernel<<<g_nsm, THREADS, g_smem>>>(g_mapHi, g_mapLo,
                                                   x, W, b, out, n_tok, g_hi);
}